// round 15
// baseline (speedup 1.0000x reference)
#include <cuda_runtime.h>
#include <cuda_bf16.h>
#include <cstdint>

// Problem constants
#define N_NODES 50000
#define E_EDGES 1600000
#define D_IN    64
#define HID     128
#define D_OUT   64
#define CAP     96      // per-node neighbor slot capacity (max degree ~58, 11-sigma)

// Device scratch (static globals; no runtime allocation)
__device__ __align__(16) float g_agg1[N_NODES * D_IN];      // 12.8 MB
__device__ __align__(16) float g_h1  [N_NODES * HID];       // 25.6 MB (fp32, gemm23 self-phase)
__device__ __align__(16) __nv_bfloat16 g_h1b[N_NODES * HID];// 12.8 MB (bf16, agg2 gather)
__device__ __align__(16) __nv_bfloat16 g_xb [N_NODES * D_IN];// 6.4 MB (bf16 x, agg1 gather)
__device__ __align__(16) float g_agg2[N_NODES * HID];       // 25.6 MB
__device__ __align__(16) int   g_deg [N_NODES];
__device__ __align__(16) int   g_slots[N_NODES * CAP];      // 19.2 MB

// ---------------------------------------------------------------------------
// Helpers
// ---------------------------------------------------------------------------
__device__ __forceinline__ uint32_t f2tf(float f) {
    uint32_t u;
    asm("cvt.rna.tf32.f32 %0, %1;" : "=r"(u) : "f"(f));
    return u;
}

__device__ __forceinline__ uint32_t bf2_to_u32(__nv_bfloat162 h) {
    union { __nv_bfloat162 h; uint32_t u; } c; c.h = h; return c.u;
}
__device__ __forceinline__ float2 u32_to_f2(uint32_t u) {
    union { uint32_t u; __nv_bfloat162 h; } c; c.u = u;
    return __bfloat1622float2(c.h);
}

__device__ __forceinline__ void mma_tf32(float* c, const uint32_t* a,
                                         uint32_t b0, uint32_t b1) {
    asm volatile(
        "mma.sync.aligned.m16n8k8.row.col.f32.tf32.tf32.f32 "
        "{%0,%1,%2,%3}, {%4,%5,%6,%7}, {%8,%9}, {%0,%1,%2,%3};"
        : "+f"(c[0]), "+f"(c[1]), "+f"(c[2]), "+f"(c[3])
        : "r"(a[0]), "r"(a[1]), "r"(a[2]), "r"(a[3]), "r"(b0), "r"(b1));
}

// ---------------------------------------------------------------------------
// Single-pass neighbor bucketing + bf16 copy of x
// ---------------------------------------------------------------------------
__global__ void zero_deg_kernel() {
    int i = blockIdx.x * blockDim.x + threadIdx.x;
    if (i < N_NODES) g_deg[i] = 0;
}

__global__ void xb_kernel(const float* __restrict__ x) {
    // 8 floats per thread -> uint4 of bf16x2
    int i = blockIdx.x * blockDim.x + threadIdx.x;   // N_NODES*D_IN/8 threads
    if (i >= N_NODES * D_IN / 8) return;
    const float4* xf = (const float4*)x;
    float4 a = xf[i * 2], b = xf[i * 2 + 1];
    uint4 o;
    o.x = bf2_to_u32(__float22bfloat162_rn(make_float2(a.x, a.y)));
    o.y = bf2_to_u32(__float22bfloat162_rn(make_float2(a.z, a.w)));
    o.z = bf2_to_u32(__float22bfloat162_rn(make_float2(b.x, b.y)));
    o.w = bf2_to_u32(__float22bfloat162_rn(make_float2(b.z, b.w)));
    ((uint4*)g_xb)[i] = o;
}

__global__ void bucket_direct_kernel(const int* __restrict__ ei) {
    int t = blockIdx.x * blockDim.x + threadIdx.x;
    int e4 = t * 4;
    if (e4 >= E_EDGES) return;
    int4 s4 = *(const int4*)(ei + e4);
    int4 d4 = *(const int4*)(ei + E_EDGES + e4);
#pragma unroll
    for (int q = 0; q < 4; q++) {
        int s = (q == 0) ? s4.x : (q == 1) ? s4.y : (q == 2) ? s4.z : s4.w;
        int d = (q == 0) ? d4.x : (q == 1) ? d4.y : (q == 2) ? d4.z : d4.w;
        if ((unsigned)s < N_NODES && (unsigned)d < N_NODES) {
            int pos = atomicAdd(&g_deg[d], 1);
            if (pos < CAP) g_slots[d * CAP + pos] = s;
            else           atomicSub(&g_deg[d], 1);   // statistically unreachable
        }
    }
}

// ---------------------------------------------------------------------------
// Gather-aggregation: one warp per destination node
// ---------------------------------------------------------------------------
__global__ void __launch_bounds__(256)
agg1_kernel() {   // bf16 gather of x copy (halves L2 traffic) -> fp32 accum
    int w = (blockIdx.x * blockDim.x + threadIdx.x) >> 5;
    if (w >= N_NODES) return;
    int lane = threadIdx.x & 31;
    int deg = g_deg[w];
    const int* slots = g_slots + w * CAP;
    const uint32_t* xb = (const uint32_t*)g_xb;   // 1 uint = 2 bf16 = lane's 2 cols
    float2 accA = make_float2(0.f, 0.f), accB = make_float2(0.f, 0.f);
    int j = 0;
    for (; j + 8 <= deg; j += 8) {
        int s[8];
#pragma unroll
        for (int q = 0; q < 8; q++) s[q] = slots[j + q];
        uint32_t v[8];
#pragma unroll
        for (int q = 0; q < 8; q++) v[q] = xb[(size_t)s[q] * 32 + lane];
#pragma unroll
        for (int q = 0; q < 8; q += 2) {
            float2 a = u32_to_f2(v[q]);
            float2 b = u32_to_f2(v[q + 1]);
            accA.x += a.x; accA.y += a.y;
            accB.x += b.x; accB.y += b.y;
        }
    }
    for (; j < deg; j++) {
        float2 a = u32_to_f2(xb[(size_t)slots[j] * 32 + lane]);
        accA.x += a.x; accA.y += a.y;
    }
    float inv = 1.0f / fmaxf((float)deg, 1.0f);
    float2 acc = make_float2((accA.x + accB.x) * inv, (accA.y + accB.y) * inv);
    ((float2*)g_agg1)[(size_t)w * 32 + lane] = acc;
}

__global__ void __launch_bounds__(256)
agg2_kernel() {   // bf16 gather (h1 post-ReLU) -> fp32 accum
    int w = (blockIdx.x * blockDim.x + threadIdx.x) >> 5;
    if (w >= N_NODES) return;
    int lane = threadIdx.x & 31;
    int deg = g_deg[w];
    const int* slots = g_slots + w * CAP;
    const uint2* hb = (const uint2*)g_h1b;
    float4 accA = make_float4(0.f, 0.f, 0.f, 0.f);
    float4 accB = make_float4(0.f, 0.f, 0.f, 0.f);
    int j = 0;
    for (; j + 8 <= deg; j += 8) {
        int s[8];
#pragma unroll
        for (int q = 0; q < 8; q++) s[q] = slots[j + q];
        uint2 v[8];
#pragma unroll
        for (int q = 0; q < 8; q++) v[q] = hb[(size_t)s[q] * 32 + lane];
#pragma unroll
        for (int q = 0; q < 8; q += 2) {
            float2 a0 = u32_to_f2(v[q].x);
            float2 a1 = u32_to_f2(v[q].y);
            float2 b0 = u32_to_f2(v[q + 1].x);
            float2 b1 = u32_to_f2(v[q + 1].y);
            accA.x += a0.x; accA.y += a0.y; accA.z += a1.x; accA.w += a1.y;
            accB.x += b0.x; accB.y += b0.y; accB.z += b1.x; accB.w += b1.y;
        }
    }
    for (; j < deg; j++) {
        uint2 v = hb[(size_t)slots[j] * 32 + lane];
        float2 a0 = u32_to_f2(v.x);
        float2 a1 = u32_to_f2(v.y);
        accA.x += a0.x; accA.y += a0.y; accA.z += a1.x; accA.w += a1.y;
    }
    float inv = 1.0f / fmaxf((float)deg, 1.0f);
    float4 acc = make_float4((accA.x + accB.x) * inv, (accA.y + accB.y) * inv,
                             (accA.z + accB.z) * inv, (accA.w + accB.w) * inv);
    ((float4*)g_agg2)[(size_t)w * 32 + lane] = acc;
}

// ---------------------------------------------------------------------------
// Tensor-core GEMM building blocks (tf32 mma.sync.m16n8k8)
// Block tile 128x128, 8 warps 4(m) x 2(n). Double-buffered smem pipeline.
// ---------------------------------------------------------------------------
#define SA_STRIDE 36
#define SW_STRIDE 136
#define SA_U32 (128 * SA_STRIDE)   // 4608
#define SW_U32 (32 * SW_STRIDE)    // 4352

template<int K>
__device__ __forceinline__ void ldA(float4* v, const float* A,
                                    int r0, int k0, int tid) {
#pragma unroll
    for (int u = 0; u < 4; u++) {
        int i = tid + u * 256;
        int row = i >> 3, kq = i & 7;
        int r = r0 + row;
        v[u] = (r < N_NODES) ? *(const float4*)(A + (size_t)r * K + k0 + kq * 4)
                             : make_float4(0.f, 0.f, 0.f, 0.f);
    }
}
__device__ __forceinline__ void stA(uint32_t* sA, const float4* v, int tid) {
#pragma unroll
    for (int u = 0; u < 4; u++) {
        int i = tid + u * 256;
        int row = i >> 3, kq = i & 7;
        *(uint4*)&sA[row * SA_STRIDE + kq * 4] =
            make_uint4(f2tf(v[u].x), f2tf(v[u].y), f2tf(v[u].z), f2tf(v[u].w));
    }
}
__device__ __forceinline__ void ldW(float4* v, const float* W, int k0, int tid) {
#pragma unroll
    for (int u = 0; u < 4; u++) {
        int i = tid + u * 256;
        int k = i >> 5, n4 = (i & 31) * 4;
        v[u] = *(const float4*)(W + (size_t)(k0 + k) * HID + n4);
    }
}
__device__ __forceinline__ void stW(uint32_t* sW, const float4* v, int tid) {
#pragma unroll
    for (int u = 0; u < 4; u++) {
        int i = tid + u * 256;
        int k = i >> 5, n4 = (i & 31) * 4;
        *(uint4*)&sW[k * SW_STRIDE + n4] =
            make_uint4(f2tf(v[u].x), f2tf(v[u].y), f2tf(v[u].z), f2tf(v[u].w));
    }
}

__device__ __forceinline__ void mma_chunk(float (*acc)[8][4],
                                          const uint32_t* sA, const uint32_t* sW,
                                          int m0, int n0, int g, int tg) {
#pragma unroll
    for (int kk = 0; kk < 32; kk += 8) {
        uint32_t a[2][4];
#pragma unroll
        for (int mf = 0; mf < 2; mf++) {
            int rb = m0 + mf * 16;
            a[mf][0] = sA[(rb + g)     * SA_STRIDE + kk + tg];
            a[mf][1] = sA[(rb + g + 8) * SA_STRIDE + kk + tg];
            a[mf][2] = sA[(rb + g)     * SA_STRIDE + kk + tg + 4];
            a[mf][3] = sA[(rb + g + 8) * SA_STRIDE + kk + tg + 4];
        }
#pragma unroll
        for (int nf = 0; nf < 8; nf++) {
            int nb = n0 + nf * 8 + g;
            uint32_t b0 = sW[(kk + tg)     * SW_STRIDE + nb];
            uint32_t b1 = sW[(kk + tg + 4) * SW_STRIDE + nb];
            mma_tf32(acc[0][nf], a[0], b0, b1);
            mma_tf32(acc[1][nf], a[1], b0, b1);
        }
    }
}

// ---------------------------------------------------------------------------
// Layer-1 (double-buffered): h1 = relu(agg1@Wl1 + x@Wr1 + b1) -> fp32 + bf16
// Dyn smem: 2*(sA + sW) = 71680 B, occ 2.
// ---------------------------------------------------------------------------
#define SMEM1_U32 (2 * (SA_U32 + SW_U32))

__global__ void __launch_bounds__(256, 2)
gemm1_kernel(const float* __restrict__ xin,
             const float* __restrict__ Wl,
             const float* __restrict__ Wr,
             const float* __restrict__ bias)
{
    extern __shared__ uint32_t smem[];
    uint32_t* sAb[2] = { smem, smem + SA_U32 };
    uint32_t* sWb[2] = { smem + 2 * SA_U32, smem + 2 * SA_U32 + SW_U32 };

    const int tid  = threadIdx.x;
    const int wid  = tid >> 5;
    const int lane = tid & 31;
    const int g    = lane >> 2;
    const int tg   = lane & 3;
    const int m0   = (wid & 3) * 32;
    const int n0   = (wid >> 2) * 64;
    const int r0   = blockIdx.x * 128;

    float acc[2][8][4];
#pragma unroll
    for (int mf = 0; mf < 2; mf++)
#pragma unroll
        for (int nf = 0; nf < 8; nf++)
#pragma unroll
            for (int q = 0; q < 4; q++) acc[mf][nf][q] = 0.f;

    const float* As[2] = { g_agg1, xin };
    const float* Ws[2] = { Wl, Wr };

    float4 vA[4], vW[4];
    ldA<D_IN>(vA, As[0], r0, 0, tid);
    ldW(vW, Ws[0], 0, tid);
    stA(sAb[0], vA, tid);
    stW(sWb[0], vW, tid);
    __syncthreads();

#pragma unroll
    for (int c = 0; c < 4; c++) {          // chunk: ph=c>>1, k0=(c&1)*32
        if (c < 3) {
            int ph = (c + 1) >> 1, k0 = ((c + 1) & 1) * 32;
            ldA<D_IN>(vA, As[ph], r0, k0, tid);
            ldW(vW, Ws[ph], k0, tid);
        }
        mma_chunk(acc, sAb[c & 1], sWb[c & 1], m0, n0, g, tg);
        if (c < 3) {
            stA(sAb[(c + 1) & 1], vA, tid);
            stW(sWb[(c + 1) & 1], vW, tid);
            __syncthreads();
        }
    }

    // Epilogue: bias + relu -> g_h1 (fp32) + g_h1b (bf16)
#pragma unroll
    for (int mf = 0; mf < 2; mf++) {
        int rbase = r0 + m0 + mf * 16;
#pragma unroll
        for (int nf = 0; nf < 8; nf++) {
            int c = n0 + nf * 8 + 2 * tg;
            float b0 = bias[c], b1 = bias[c + 1];
            int ra = rbase + g, rb = rbase + g + 8;
            if (ra < N_NODES) {
                float2 v = make_float2(fmaxf(acc[mf][nf][0] + b0, 0.f),
                                       fmaxf(acc[mf][nf][1] + b1, 0.f));
                *(float2*)(g_h1 + (size_t)ra * HID + c) = v;
                *(__nv_bfloat162*)(g_h1b + (size_t)ra * HID + c) = __float22bfloat162_rn(v);
            }
            if (rb < N_NODES) {
                float2 v = make_float2(fmaxf(acc[mf][nf][2] + b0, 0.f),
                                       fmaxf(acc[mf][nf][3] + b1, 0.f));
                *(float2*)(g_h1 + (size_t)rb * HID + c) = v;
                *(__nv_bfloat162*)(g_h1b + (size_t)rb * HID + c) = __float22bfloat162_rn(v);
            }
        }
    }
}

// ---------------------------------------------------------------------------
// Fused layers 2+3 (double-buffered phase A):
//   h2 = relu(agg2@Wl2 + h1@Wr2 + b2)  staged in SMEM tf32
//   out = h2 @ Wo + bo
// Dyn smem: 2*(sA+sW) + sH2 = 139264 B, occ 1.
// ---------------------------------------------------------------------------
#define SH2_STRIDE 132
#define SWO_STRIDE 132
#define SMEM23_U32 (2 * (SA_U32 + SW_U32) + 128 * SH2_STRIDE)

__global__ void __launch_bounds__(256, 1)
gemm23_kernel(const float* __restrict__ Wl,
              const float* __restrict__ Wr,
              const float* __restrict__ bias2,
              const float* __restrict__ Wo,
              const float* __restrict__ biasO,
              float* __restrict__ outp)
{
    extern __shared__ uint32_t smem[];
    uint32_t* sAb[2] = { smem, smem + SA_U32 };
    uint32_t* sWb[2] = { smem + 2 * SA_U32, smem + 2 * SA_U32 + SW_U32 };
    uint32_t* sWoT   = smem;                               // union with sA (phase B)
    uint32_t* sH2    = smem + 2 * (SA_U32 + SW_U32);       // 128*132

    const int tid  = threadIdx.x;
    const int wid  = tid >> 5;
    const int lane = tid & 31;
    const int g    = lane >> 2;
    const int tg   = lane & 3;
    const int m0   = (wid & 3) * 32;
    const int n0   = (wid >> 2) * 64;
    const int r0   = blockIdx.x * 128;

    float acc[2][8][4];
#pragma unroll
    for (int mf = 0; mf < 2; mf++)
#pragma unroll
        for (int nf = 0; nf < 8; nf++)
#pragma unroll
            for (int q = 0; q < 4; q++) acc[mf][nf][q] = 0.f;

    const float* As[2] = { g_agg2, g_h1 };
    const float* Ws[2] = { Wl, Wr };

    float4 vA[4], vW[4];
    ldA<HID>(vA, As[0], r0, 0, tid);
    ldW(vW, Ws[0], 0, tid);
    stA(sAb[0], vA, tid);
    stW(sWb[0], vW, tid);
    __syncthreads();

#pragma unroll
    for (int c = 0; c < 8; c++) {          // chunk: ph=c>>2, k0=(c&3)*32
        if (c < 7) {
            int ph = (c + 1) >> 2, k0 = ((c + 1) & 3) * 32;
            ldA<HID>(vA, As[ph], r0, k0, tid);
            ldW(vW, Ws[ph], k0, tid);
        }
        mma_chunk(acc, sAb[c & 1], sWb[c & 1], m0, n0, g, tg);
        if (c < 7) {
            stA(sAb[(c + 1) & 1], vA, tid);
            stW(sWb[(c + 1) & 1], vW, tid);
            __syncthreads();
        }
    }

    // Stage h2 = relu(acc + b2) into sH2 as tf32 bits
#pragma unroll
    for (int mf = 0; mf < 2; mf++) {
        int rbase = m0 + mf * 16;
#pragma unroll
        for (int nf = 0; nf < 8; nf++) {
            int c = n0 + nf * 8 + 2 * tg;
            float b0 = bias2[c], b1 = bias2[c + 1];
            sH2[(rbase + g) * SH2_STRIDE + c]         = f2tf(fmaxf(acc[mf][nf][0] + b0, 0.f));
            sH2[(rbase + g) * SH2_STRIDE + c + 1]     = f2tf(fmaxf(acc[mf][nf][1] + b1, 0.f));
            sH2[(rbase + g + 8) * SH2_STRIDE + c]     = f2tf(fmaxf(acc[mf][nf][2] + b0, 0.f));
            sH2[(rbase + g + 8) * SH2_STRIDE + c + 1] = f2tf(fmaxf(acc[mf][nf][3] + b1, 0.f));
        }
    }
    __syncthreads();   // sH2 complete; everyone done reading sA/sW

    // Fill sWoT[n][k] = tf32(Wo[k][n])
#pragma unroll
    for (int i = tid; i < HID * D_OUT; i += 256) {
        int k = i >> 6;
        int n = i & 63;
        sWoT[n * SWO_STRIDE + k] = f2tf(Wo[i]);
    }
    __syncthreads();

    // Phase B: out = sH2 @ Wo + bo  (128x64, K=128)
    {
        const int n0b = (wid >> 2) * 32;
        float acc2[2][4][4];
#pragma unroll
        for (int mf = 0; mf < 2; mf++)
#pragma unroll
            for (int nf = 0; nf < 4; nf++)
#pragma unroll
                for (int q = 0; q < 4; q++) acc2[mf][nf][q] = 0.f;

#pragma unroll 4
        for (int kk = 0; kk < HID; kk += 8) {
            uint32_t a[2][4];
#pragma unroll
            for (int mf = 0; mf < 2; mf++) {
                int rb = m0 + mf * 16;
                a[mf][0] = sH2[(rb + g)     * SH2_STRIDE + kk + tg];
                a[mf][1] = sH2[(rb + g + 8) * SH2_STRIDE + kk + tg];
                a[mf][2] = sH2[(rb + g)     * SH2_STRIDE + kk + tg + 4];
                a[mf][3] = sH2[(rb + g + 8) * SH2_STRIDE + kk + tg + 4];
            }
#pragma unroll
            for (int nf = 0; nf < 4; nf++) {
                int nb = n0b + nf * 8 + g;
                uint32_t b0 = sWoT[nb * SWO_STRIDE + kk + tg];
                uint32_t b1 = sWoT[nb * SWO_STRIDE + kk + tg + 4];
                mma_tf32(acc2[0][nf], a[0], b0, b1);
                mma_tf32(acc2[1][nf], a[1], b0, b1);
            }
        }

#pragma unroll
        for (int mf = 0; mf < 2; mf++) {
            int rbase = r0 + m0 + mf * 16;
#pragma unroll
            for (int nf = 0; nf < 4; nf++) {
                int c = n0b + nf * 8 + 2 * tg;
                float b0 = biasO[c], b1 = biasO[c + 1];
                int ra = rbase + g, rb = rbase + g + 8;
                if (ra < N_NODES) {
                    float2 v = make_float2(acc2[mf][nf][0] + b0,
                                           acc2[mf][nf][1] + b1);
                    *(float2*)(outp + (size_t)ra * D_OUT + c) = v;
                }
                if (rb < N_NODES) {
                    float2 v = make_float2(acc2[mf][nf][2] + b0,
                                           acc2[mf][nf][3] + b1);
                    *(float2*)(outp + (size_t)rb * D_OUT + c) = v;
                }
            }
        }
    }
}

// ---------------------------------------------------------------------------
// Launch
// ---------------------------------------------------------------------------
extern "C" void kernel_launch(void* const* d_in, const int* in_sizes, int n_in,
                              void* d_out, int out_size) {
    const float* x   = (const float*)d_in[0];
    const int*   ei  = (const int*)d_in[1];   // int32 (JAX default demotion)
    const float* Wl1 = (const float*)d_in[2];
    const float* b1  = (const float*)d_in[3];
    const float* Wr1 = (const float*)d_in[4];
    const float* Wl2 = (const float*)d_in[5];
    const float* b2  = (const float*)d_in[6];
    const float* Wr2 = (const float*)d_in[7];
    const float* Wo  = (const float*)d_in[8];
    const float* bo  = (const float*)d_in[9];
    float* out = (float*)d_out;

    cudaFuncSetAttribute(gemm1_kernel,
                         cudaFuncAttributeMaxDynamicSharedMemorySize,
                         SMEM1_U32 * 4);
    cudaFuncSetAttribute(gemm23_kernel,
                         cudaFuncAttributeMaxDynamicSharedMemorySize,
                         SMEM23_U32 * 4);

    // Preprocessing: degree zero, bf16 x copy, single-pass bucketing
    zero_deg_kernel<<<(N_NODES + 255) / 256, 256>>>();
    xb_kernel<<<(N_NODES * D_IN / 8 + 255) / 256, 256>>>(x);
    bucket_direct_kernel<<<(E_EDGES / 4 + 255) / 256, 256>>>(ei);

    constexpr int WGRID = (N_NODES * 32 + 255) / 256;   // warp-per-node grids
    constexpr int GB    = (N_NODES + 127) / 128;        // 391

    agg1_kernel<<<WGRID, 256>>>();
    gemm1_kernel<<<GB, 256, SMEM1_U32 * 4>>>(x, Wl1, Wr1, b1);

    agg2_kernel<<<WGRID, 256>>>();
    gemm23_kernel<<<GB, 256, SMEM23_U32 * 4>>>(Wl2, Wr2, b2, Wo, bo, out);
}

// round 16
// speedup vs baseline: 1.0477x; 1.0477x over previous
#include <cuda_runtime.h>
#include <cuda_bf16.h>
#include <cstdint>

// Problem constants
#define N_NODES 50000
#define E_EDGES 1600000
#define D_IN    64
#define HID     128
#define D_OUT   64
#define CAP     96      // per-node neighbor slot capacity (max degree ~58, 11-sigma)

// Device scratch (static globals; no runtime allocation)
__device__ __align__(16) float g_agg1[N_NODES * D_IN];      // 12.8 MB
__device__ __align__(16) float g_h1  [N_NODES * HID];       // 25.6 MB (fp32, gemm23 self-phase)
__device__ __align__(16) __nv_bfloat16 g_h1b[N_NODES * HID];// 12.8 MB (bf16, agg2 gather)
__device__ __align__(16) float g_agg2[N_NODES * HID];       // 25.6 MB
__device__ __align__(16) int   g_deg [N_NODES];
__device__ __align__(16) int   g_slots[N_NODES * CAP];      // 19.2 MB

// ---------------------------------------------------------------------------
// Helpers
// ---------------------------------------------------------------------------
__device__ __forceinline__ uint32_t f2tf(float f) {
    uint32_t u;
    asm("cvt.rna.tf32.f32 %0, %1;" : "=r"(u) : "f"(f));
    return u;
}

__device__ __forceinline__ float2 u32_to_f2(uint32_t u) {
    union { uint32_t u; __nv_bfloat162 h; } c; c.u = u;
    return __bfloat1622float2(c.h);
}

__device__ __forceinline__ void mma_tf32(float* c, const uint32_t* a,
                                         uint32_t b0, uint32_t b1) {
    asm volatile(
        "mma.sync.aligned.m16n8k8.row.col.f32.tf32.tf32.f32 "
        "{%0,%1,%2,%3}, {%4,%5,%6,%7}, {%8,%9}, {%0,%1,%2,%3};"
        : "+f"(c[0]), "+f"(c[1]), "+f"(c[2]), "+f"(c[3])
        : "r"(a[0]), "r"(a[1]), "r"(a[2]), "r"(a[3]), "r"(b0), "r"(b1));
}

// ---------------------------------------------------------------------------
// Single-pass neighbor bucketing. 8 edges/thread: all 8 atomics issue before
// any return is consumed -> MLP 8 over the 318-cyc ATOMG latency.
// ---------------------------------------------------------------------------
__global__ void zero_deg_kernel() {
    int i = blockIdx.x * blockDim.x + threadIdx.x;
    if (i < N_NODES) g_deg[i] = 0;
}

__global__ void bucket_direct_kernel(const int* __restrict__ ei) {
    int t = blockIdx.x * blockDim.x + threadIdx.x;
    int e8 = t * 8;
    if (e8 >= E_EDGES) return;
    int4 sa = *(const int4*)(ei + e8);
    int4 sb = *(const int4*)(ei + e8 + 4);
    int4 da = *(const int4*)(ei + E_EDGES + e8);
    int4 db = *(const int4*)(ei + E_EDGES + e8 + 4);
    int s[8] = { sa.x, sa.y, sa.z, sa.w, sb.x, sb.y, sb.z, sb.w };
    int d[8] = { da.x, da.y, da.z, da.w, db.x, db.y, db.z, db.w };
    int pos[8];
#pragma unroll
    for (int q = 0; q < 8; q++) {
        if ((unsigned)s[q] < N_NODES && (unsigned)d[q] < N_NODES)
            pos[q] = atomicAdd(&g_deg[d[q]], 1);
        else
            pos[q] = -1;
    }
#pragma unroll
    for (int q = 0; q < 8; q++) {
        if (pos[q] >= 0) {
            if (pos[q] < CAP) g_slots[d[q] * CAP + pos[q]] = s[q];
            else              atomicSub(&g_deg[d[q]], 1);   // statistically unreachable
        }
    }
}

// ---------------------------------------------------------------------------
// Gather-aggregation: one warp per destination node
// ---------------------------------------------------------------------------
__global__ void __launch_bounds__(256)
agg1_kernel(const float* __restrict__ x) {   // fp32 float2/lane gather
    int w = (blockIdx.x * blockDim.x + threadIdx.x) >> 5;
    if (w >= N_NODES) return;
    int lane = threadIdx.x & 31;
    int deg = g_deg[w];
    const int* slots = g_slots + w * CAP;
    const float2* xb = (const float2*)x;
    float2 accA = make_float2(0.f, 0.f), accB = make_float2(0.f, 0.f);
    int j = 0;
    for (; j + 8 <= deg; j += 8) {
        int s[8];
#pragma unroll
        for (int q = 0; q < 8; q++) s[q] = slots[j + q];
        float2 v[8];
#pragma unroll
        for (int q = 0; q < 8; q++) v[q] = xb[(size_t)s[q] * 32 + lane];
#pragma unroll
        for (int q = 0; q < 8; q += 2) {
            accA.x += v[q].x;     accA.y += v[q].y;
            accB.x += v[q + 1].x; accB.y += v[q + 1].y;
        }
    }
    for (; j < deg; j++) {
        int s = slots[j];
        float2 v = xb[(size_t)s * 32 + lane];
        accA.x += v.x; accA.y += v.y;
    }
    float inv = 1.0f / fmaxf((float)deg, 1.0f);
    float2 acc = make_float2((accA.x + accB.x) * inv, (accA.y + accB.y) * inv);
    ((float2*)g_agg1)[(size_t)w * 32 + lane] = acc;
}

__global__ void __launch_bounds__(256)
agg2_kernel() {   // bf16 gather (h1 post-ReLU, no cancellation) -> fp32 accum
    int w = (blockIdx.x * blockDim.x + threadIdx.x) >> 5;
    if (w >= N_NODES) return;
    int lane = threadIdx.x & 31;
    int deg = g_deg[w];
    const int* slots = g_slots + w * CAP;
    const uint2* hb = (const uint2*)g_h1b;
    float4 accA = make_float4(0.f, 0.f, 0.f, 0.f);
    float4 accB = make_float4(0.f, 0.f, 0.f, 0.f);
    int j = 0;
    for (; j + 8 <= deg; j += 8) {
        int s[8];
#pragma unroll
        for (int q = 0; q < 8; q++) s[q] = slots[j + q];
        uint2 v[8];
#pragma unroll
        for (int q = 0; q < 8; q++) v[q] = hb[(size_t)s[q] * 32 + lane];
#pragma unroll
        for (int q = 0; q < 8; q += 2) {
            float2 a0 = u32_to_f2(v[q].x);
            float2 a1 = u32_to_f2(v[q].y);
            float2 b0 = u32_to_f2(v[q + 1].x);
            float2 b1 = u32_to_f2(v[q + 1].y);
            accA.x += a0.x; accA.y += a0.y; accA.z += a1.x; accA.w += a1.y;
            accB.x += b0.x; accB.y += b0.y; accB.z += b1.x; accB.w += b1.y;
        }
    }
    for (; j < deg; j++) {
        uint2 v = hb[(size_t)slots[j] * 32 + lane];
        float2 a0 = u32_to_f2(v.x);
        float2 a1 = u32_to_f2(v.y);
        accA.x += a0.x; accA.y += a0.y; accA.z += a1.x; accA.w += a1.y;
    }
    float inv = 1.0f / fmaxf((float)deg, 1.0f);
    float4 acc = make_float4((accA.x + accB.x) * inv, (accA.y + accB.y) * inv,
                             (accA.z + accB.z) * inv, (accA.w + accB.w) * inv);
    ((float4*)g_agg2)[(size_t)w * 32 + lane] = acc;
}

// ---------------------------------------------------------------------------
// Tensor-core GEMM building blocks (tf32 mma.sync.m16n8k8)
// Block tile 128x128, 8 warps 4(m) x 2(n): warp tile 32x64.
// ---------------------------------------------------------------------------
#define SA_STRIDE 36
#define SW_STRIDE 136
#define SA_U32 (128 * SA_STRIDE)   // 4608
#define SW_U32 (32 * SW_STRIDE)    // 4352

template<int K>
__device__ __forceinline__ void ldA(float4* v, const float* A,
                                    int r0, int k0, int tid) {
#pragma unroll
    for (int u = 0; u < 4; u++) {
        int i = tid + u * 256;
        int row = i >> 3, kq = i & 7;
        int r = r0 + row;
        v[u] = (r < N_NODES) ? *(const float4*)(A + (size_t)r * K + k0 + kq * 4)
                             : make_float4(0.f, 0.f, 0.f, 0.f);
    }
}
__device__ __forceinline__ void stA(uint32_t* sA, const float4* v, int tid) {
#pragma unroll
    for (int u = 0; u < 4; u++) {
        int i = tid + u * 256;
        int row = i >> 3, kq = i & 7;
        *(uint4*)&sA[row * SA_STRIDE + kq * 4] =
            make_uint4(f2tf(v[u].x), f2tf(v[u].y), f2tf(v[u].z), f2tf(v[u].w));
    }
}
__device__ __forceinline__ void ldW(float4* v, const float* W, int k0, int tid) {
#pragma unroll
    for (int u = 0; u < 4; u++) {
        int i = tid + u * 256;
        int k = i >> 5, n4 = (i & 31) * 4;
        v[u] = *(const float4*)(W + (size_t)(k0 + k) * HID + n4);
    }
}
__device__ __forceinline__ void stW(uint32_t* sW, const float4* v, int tid) {
#pragma unroll
    for (int u = 0; u < 4; u++) {
        int i = tid + u * 256;
        int k = i >> 5, n4 = (i & 31) * 4;
        *(uint4*)&sW[k * SW_STRIDE + n4] =
            make_uint4(f2tf(v[u].x), f2tf(v[u].y), f2tf(v[u].z), f2tf(v[u].w));
    }
}

__device__ __forceinline__ void mma_chunk(float (*acc)[8][4],
                                          const uint32_t* sA, const uint32_t* sW,
                                          int m0, int n0, int g, int tg) {
#pragma unroll
    for (int kk = 0; kk < 32; kk += 8) {
        uint32_t a[2][4];
#pragma unroll
        for (int mf = 0; mf < 2; mf++) {
            int rb = m0 + mf * 16;
            a[mf][0] = sA[(rb + g)     * SA_STRIDE + kk + tg];
            a[mf][1] = sA[(rb + g + 8) * SA_STRIDE + kk + tg];
            a[mf][2] = sA[(rb + g)     * SA_STRIDE + kk + tg + 4];
            a[mf][3] = sA[(rb + g + 8) * SA_STRIDE + kk + tg + 4];
        }
#pragma unroll
        for (int nf = 0; nf < 8; nf++) {
            int nb = n0 + nf * 8 + g;
            uint32_t b0 = sW[(kk + tg)     * SW_STRIDE + nb];
            uint32_t b1 = sW[(kk + tg + 4) * SW_STRIDE + nb];
            mma_tf32(acc[0][nf], a[0], b0, b1);
            mma_tf32(acc[1][nf], a[1], b0, b1);
        }
    }
}

// ---------------------------------------------------------------------------
// Layer-1 (double-buffered, occ 2): h1 = relu(agg1@Wl1 + x@Wr1 + b1)
// Dyn smem: 2*(sA + sW) = 71680 B.
// ---------------------------------------------------------------------------
#define SMEM1_U32 (2 * (SA_U32 + SW_U32))

__global__ void __launch_bounds__(256, 2)
gemm1_kernel(const float* __restrict__ xin,
             const float* __restrict__ Wl,
             const float* __restrict__ Wr,
             const float* __restrict__ bias)
{
    extern __shared__ uint32_t smem[];
    uint32_t* sAb[2] = { smem, smem + SA_U32 };
    uint32_t* sWb[2] = { smem + 2 * SA_U32, smem + 2 * SA_U32 + SW_U32 };

    const int tid  = threadIdx.x;
    const int wid  = tid >> 5;
    const int lane = tid & 31;
    const int g    = lane >> 2;
    const int tg   = lane & 3;
    const int m0   = (wid & 3) * 32;
    const int n0   = (wid >> 2) * 64;
    const int r0   = blockIdx.x * 128;

    float acc[2][8][4];
#pragma unroll
    for (int mf = 0; mf < 2; mf++)
#pragma unroll
        for (int nf = 0; nf < 8; nf++)
#pragma unroll
            for (int q = 0; q < 4; q++) acc[mf][nf][q] = 0.f;

    const float* As[2] = { g_agg1, xin };
    const float* Ws[2] = { Wl, Wr };

    float4 vA[4], vW[4];
    ldA<D_IN>(vA, As[0], r0, 0, tid);
    ldW(vW, Ws[0], 0, tid);
    stA(sAb[0], vA, tid);
    stW(sWb[0], vW, tid);
    __syncthreads();

#pragma unroll
    for (int c = 0; c < 4; c++) {          // chunk: ph=c>>1, k0=(c&1)*32
        if (c < 3) {
            int ph = (c + 1) >> 1, k0 = ((c + 1) & 1) * 32;
            ldA<D_IN>(vA, As[ph], r0, k0, tid);
            ldW(vW, Ws[ph], k0, tid);
        }
        mma_chunk(acc, sAb[c & 1], sWb[c & 1], m0, n0, g, tg);
        if (c < 3) {
            stA(sAb[(c + 1) & 1], vA, tid);
            stW(sWb[(c + 1) & 1], vW, tid);
            __syncthreads();
        }
    }

    // Epilogue: bias + relu -> g_h1 (fp32) + g_h1b (bf16)
#pragma unroll
    for (int mf = 0; mf < 2; mf++) {
        int rbase = r0 + m0 + mf * 16;
#pragma unroll
        for (int nf = 0; nf < 8; nf++) {
            int c = n0 + nf * 8 + 2 * tg;
            float b0 = bias[c], b1 = bias[c + 1];
            int ra = rbase + g, rb = rbase + g + 8;
            if (ra < N_NODES) {
                float2 v = make_float2(fmaxf(acc[mf][nf][0] + b0, 0.f),
                                       fmaxf(acc[mf][nf][1] + b1, 0.f));
                *(float2*)(g_h1 + (size_t)ra * HID + c) = v;
                *(__nv_bfloat162*)(g_h1b + (size_t)ra * HID + c) = __float22bfloat162_rn(v);
            }
            if (rb < N_NODES) {
                float2 v = make_float2(fmaxf(acc[mf][nf][2] + b0, 0.f),
                                       fmaxf(acc[mf][nf][3] + b1, 0.f));
                *(float2*)(g_h1 + (size_t)rb * HID + c) = v;
                *(__nv_bfloat162*)(g_h1b + (size_t)rb * HID + c) = __float22bfloat162_rn(v);
            }
        }
    }
}

// ---------------------------------------------------------------------------
// Fused layers 2+3 (single-buffered, occ 2 — R13 structure):
//   h2 = relu(agg2@Wl2 + h1@Wr2 + b2)  staged in SMEM tf32
//   out = h2 @ Wo + bo
// Dyn smem: sA + sW + sH2 = 103424 B; 2 CTA/SM = 207 KB <= 228 KB.
// ---------------------------------------------------------------------------
#define SH2_STRIDE 132
#define SWO_STRIDE 132
#define SMEM23_U32 (SA_U32 + SW_U32 + 128 * SH2_STRIDE)

__global__ void __launch_bounds__(256, 2)
gemm23_kernel(const float* __restrict__ Wl,
              const float* __restrict__ Wr,
              const float* __restrict__ bias2,
              const float* __restrict__ Wo,
              const float* __restrict__ biasO,
              float* __restrict__ outp)
{
    extern __shared__ uint32_t smem[];
    uint32_t* sA   = smem;                         // 4608
    uint32_t* sW   = smem + SA_U32;                // 4352
    uint32_t* sWoT = smem;                         // union with sA (phase B)
    uint32_t* sH2  = smem + SA_U32 + SW_U32;       // 128*132

    const int tid  = threadIdx.x;
    const int wid  = tid >> 5;
    const int lane = tid & 31;
    const int g    = lane >> 2;
    const int tg   = lane & 3;
    const int m0   = (wid & 3) * 32;
    const int n0   = (wid >> 2) * 64;
    const int r0   = blockIdx.x * 128;

    float acc[2][8][4];
#pragma unroll
    for (int mf = 0; mf < 2; mf++)
#pragma unroll
        for (int nf = 0; nf < 8; nf++)
#pragma unroll
            for (int q = 0; q < 4; q++) acc[mf][nf][q] = 0.f;

#pragma unroll 1
    for (int ph = 0; ph < 2; ph++) {
        const float* A = (ph == 0) ? g_agg2 : g_h1;
        const float* W = (ph == 0) ? Wl : Wr;
#pragma unroll 1
        for (int k0 = 0; k0 < HID; k0 += 32) {
            __syncthreads();
            {
                float4 vA[4], vW[4];
                ldA<HID>(vA, A, r0, k0, tid);
                ldW(vW, W, k0, tid);
                stA(sA, vA, tid);
                stW(sW, vW, tid);
            }
            __syncthreads();
            mma_chunk(acc, sA, sW, m0, n0, g, tg);
        }
    }

    // Stage h2 = relu(acc + b2) into sH2 as tf32 bits
#pragma unroll
    for (int mf = 0; mf < 2; mf++) {
        int rbase = m0 + mf * 16;
#pragma unroll
        for (int nf = 0; nf < 8; nf++) {
            int c = n0 + nf * 8 + 2 * tg;
            float b0 = bias2[c], b1 = bias2[c + 1];
            sH2[(rbase + g) * SH2_STRIDE + c]         = f2tf(fmaxf(acc[mf][nf][0] + b0, 0.f));
            sH2[(rbase + g) * SH2_STRIDE + c + 1]     = f2tf(fmaxf(acc[mf][nf][1] + b1, 0.f));
            sH2[(rbase + g + 8) * SH2_STRIDE + c]     = f2tf(fmaxf(acc[mf][nf][2] + b0, 0.f));
            sH2[(rbase + g + 8) * SH2_STRIDE + c + 1] = f2tf(fmaxf(acc[mf][nf][3] + b1, 0.f));
        }
    }
    __syncthreads();   // sH2 complete; everyone done reading sA/sW

    // Fill sWoT[n][k] = tf32(Wo[k][n])
#pragma unroll
    for (int i = tid; i < HID * D_OUT; i += 256) {
        int k = i >> 6;
        int n = i & 63;
        sWoT[n * SWO_STRIDE + k] = f2tf(Wo[i]);
    }
    __syncthreads();

    // Phase B: out = sH2 @ Wo + bo  (128x64, K=128)
    {
        const int n0b = (wid >> 2) * 32;
        float acc2[2][4][4];
#pragma unroll
        for (int mf = 0; mf < 2; mf++)
#pragma unroll
            for (int nf = 0; nf < 4; nf++)
#pragma unroll
                for (int q = 0; q < 4; q++) acc2[mf][nf][q] = 0.f;

#pragma unroll 4
        for (int kk = 0; kk < HID; kk += 8) {
            uint32_t a[2][4];
#pragma unroll
            for (int mf = 0; mf < 2; mf++) {
                int rb = m0 + mf * 16;
                a[mf][0] = sH2[(rb + g)     * SH2_STRIDE + kk + tg];
                a[mf][1] = sH2[(rb + g + 8) * SH2_STRIDE + kk + tg];
                a[mf][2] = sH2[(rb + g)     * SH2_STRIDE + kk + tg + 4];
                a[mf][3] = sH2[(rb + g + 8) * SH2_STRIDE + kk + tg + 4];
            }
#pragma unroll
            for (int nf = 0; nf < 4; nf++) {
                int nb = n0b + nf * 8 + g;
                uint32_t b0 = sWoT[nb * SWO_STRIDE + kk + tg];
                uint32_t b1 = sWoT[nb * SWO_STRIDE + kk + tg + 4];
                mma_tf32(acc2[0][nf], a[0], b0, b1);
                mma_tf32(acc2[1][nf], a[1], b0, b1);
            }
        }

#pragma unroll
        for (int mf = 0; mf < 2; mf++) {
            int rbase = r0 + m0 + mf * 16;
#pragma unroll
            for (int nf = 0; nf < 4; nf++) {
                int c = n0b + nf * 8 + 2 * tg;
                float b0 = biasO[c], b1 = biasO[c + 1];
                int ra = rbase + g, rb = rbase + g + 8;
                if (ra < N_NODES) {
                    float2 v = make_float2(acc2[mf][nf][0] + b0,
                                           acc2[mf][nf][1] + b1);
                    *(float2*)(outp + (size_t)ra * D_OUT + c) = v;
                }
                if (rb < N_NODES) {
                    float2 v = make_float2(acc2[mf][nf][2] + b0,
                                           acc2[mf][nf][3] + b1);
                    *(float2*)(outp + (size_t)rb * D_OUT + c) = v;
                }
            }
        }
    }
}

// ---------------------------------------------------------------------------
// Launch
// ---------------------------------------------------------------------------
extern "C" void kernel_launch(void* const* d_in, const int* in_sizes, int n_in,
                              void* d_out, int out_size) {
    const float* x   = (const float*)d_in[0];
    const int*   ei  = (const int*)d_in[1];   // int32 (JAX default demotion)
    const float* Wl1 = (const float*)d_in[2];
    const float* b1  = (const float*)d_in[3];
    const float* Wr1 = (const float*)d_in[4];
    const float* Wl2 = (const float*)d_in[5];
    const float* b2  = (const float*)d_in[6];
    const float* Wr2 = (const float*)d_in[7];
    const float* Wo  = (const float*)d_in[8];
    const float* bo  = (const float*)d_in[9];
    float* out = (float*)d_out;

    cudaFuncSetAttribute(gemm1_kernel,
                         cudaFuncAttributeMaxDynamicSharedMemorySize,
                         SMEM1_U32 * 4);
    cudaFuncSetAttribute(gemm23_kernel,
                         cudaFuncAttributeMaxDynamicSharedMemorySize,
                         SMEM23_U32 * 4);

    // Single-pass neighbor-list build
    zero_deg_kernel<<<(N_NODES + 255) / 256, 256>>>();
    bucket_direct_kernel<<<(E_EDGES / 8 + 255) / 256, 256>>>(ei);

    constexpr int WGRID = (N_NODES * 32 + 255) / 256;   // warp-per-node grids
    constexpr int GB    = (N_NODES + 127) / 128;        // 391

    agg1_kernel<<<WGRID, 256>>>(x);
    gemm1_kernel<<<GB, 256, SMEM1_U32 * 4>>>(x, Wl1, Wr1, b1);

    agg2_kernel<<<WGRID, 256>>>();
    gemm23_kernel<<<GB, 256, SMEM23_U32 * 4>>>(Wl2, Wr2, b2, Wo, bo, out);
}